// round 9
// baseline (speedup 1.0000x reference)
#include <cuda_runtime.h>
#include <cuda_bf16.h>

// Fused conv1(3->16)+GELU -> conv2(16->18) -> deformable bilinear sampling.
// R8: 32x32 tile, 4 px/thread in both stages (LDS.128 h-fetches, 8-way
// accumulator ILP), dynamic smem ~93KB, 2 blocks/SM.

#define TS  32          // output tile side
#define HT  34          // h tile side
#define HP  36          // s_h row pitch (floats, mult of 4 -> 16B rows)
#define IT  36          // input tile side
#define IP  40          // s_in row pitch (floats, mult of 4)
#define HH  512
#define WW  512
#define HWS (HH * WW)

#define SMEM_FLOATS (16 * HT * HP + 3 * IT * IP)   // 19584 + 4320 = 23904
#define SMEM_BYTES  (SMEM_FLOATS * 4)              // 95616 B

__constant__ float c_w1[432];    // (16,3,3,3)
__constant__ float c_b1[16];
__constant__ float c_w2[2592];   // (18,16,3,3)
__constant__ float c_b2[18];
__constant__ float c_wt[9];

// exact GELU via Abramowitz-Stegun 7.1.26 erf (|abs err| <= 1.5e-7)
__device__ __forceinline__ float gelu_fast(float x) {
    float z = 0.70710678118f * x;
    float a = fabsf(z);
    float t = __fdividef(1.0f, fmaf(0.3275911f, a, 1.0f));
    float p = fmaf(1.061405429f, t, -1.453152027f);
    p = fmaf(p, t, 1.421413741f);
    p = fmaf(p, t, -0.284496736f);
    p = fmaf(p, t, 0.254829592f);
    p = p * t;
    float e = __expf(-a * a);
    float erfa = fmaf(-p, e, 1.0f);
    float erfz = copysignf(erfa, z);
    return x * (0.5f * (1.0f + erfz));
}

__global__ __launch_bounds__(256)
void fused_residual_advection(const float* __restrict__ pm25,
                              const float* __restrict__ wind,
                              const float* __restrict__ topo,
                              float* __restrict__ out) {
    extern __shared__ float smem[];
    float* s_h  = smem;                    // [16][HT][HP]
    float* s_in = smem + 16 * HT * HP;     // [3][IT][IP]

    const int tid = threadIdx.x;
    const int b   = blockIdx.z;
    const int ty0 = blockIdx.y * TS;
    const int tx0 = blockIdx.x * TS;

    // ---- load zero-padded input tile [wind0, wind1, topo]; pad cols zeroed ----
    const float* windb = wind + (size_t)b * 2 * HWS;
    const float* topob = topo + (size_t)b * HWS;
    for (int i = tid; i < 3 * IT * IP; i += 256) {
        int c  = i / (IT * IP);
        int r  = i - c * (IT * IP);
        int iy = r / IP, ix = r - iy * IP;
        float v = 0.f;
        if (ix < IT) {
            int gy = ty0 - 2 + iy, gx = tx0 - 2 + ix;
            if ((unsigned)gy < HH && (unsigned)gx < WW)
                v = (c < 2) ? windb[c * HWS + gy * WW + gx] : topob[gy * WW + gx];
        }
        s_in[i] = v;
    }
    __syncthreads();

    // ---- stage 1: h = gelu(conv1) on 34x34 tile, 4 px/thread ----
    // 34 rows x 9 col-groups-of-4 = 306 items (last group covers 2 cols).
    for (int p = tid; p < 34 * 9; p += 256) {
        const int hy  = p / 9;
        const int hx0 = (p - hy * 9) * 4;
        const int gy  = ty0 - 1 + hy;
        const bool rowv = (unsigned)gy < HH;

        float in_reg[3][3][6];
        #pragma unroll
        for (int c = 0; c < 3; c++)
            #pragma unroll
            for (int ky = 0; ky < 3; ky++) {
                const float* row = &s_in[(c * IT + hy + ky) * IP + hx0];
                float4 A = *(const float4*)row;
                float2 C = *(const float2*)(row + 4);
                in_reg[c][ky][0] = A.x; in_reg[c][ky][1] = A.y;
                in_reg[c][ky][2] = A.z; in_reg[c][ky][3] = A.w;
                in_reg[c][ky][4] = C.x; in_reg[c][ky][5] = C.y;
            }

        #pragma unroll
        for (int o = 0; o < 16; o++) {
            float a0 = c_b1[o], a1 = a0, a2 = a0, a3 = a0;
            #pragma unroll
            for (int c = 0; c < 3; c++)
                #pragma unroll
                for (int ky = 0; ky < 3; ky++)
                    #pragma unroll
                    for (int kx = 0; kx < 3; kx++) {
                        const float w = c_w1[o * 27 + (c * 3 + ky) * 3 + kx];
                        a0 = fmaf(in_reg[c][ky][kx],     w, a0);
                        a1 = fmaf(in_reg[c][ky][kx + 1], w, a1);
                        a2 = fmaf(in_reg[c][ky][kx + 2], w, a2);
                        a3 = fmaf(in_reg[c][ky][kx + 3], w, a3);
                    }
            float* hrow = &s_h[(o * HT + hy) * HP + hx0];
            #pragma unroll
            for (int j = 0; j < 4; j++) {
                float aj = j == 0 ? a0 : j == 1 ? a1 : j == 2 ? a2 : a3;
                int hx = hx0 + j;
                if (hx < HT) {
                    bool v = rowv && (unsigned)(tx0 - 1 + hx) < WW;
                    hrow[j] = v ? gelu_fast(aj) : 0.f;
                }
            }
        }
    }
    __syncthreads();

    // ---- stage 2: 4 horizontal outputs per thread ----
    const int py  = tid >> 3;            // 0..31
    const int px4 = (tid & 7) * 4;       // 0,4,...,28
    const int gy  = ty0 + py;
    const int gx0 = tx0 + px4;
    const float* pimg = pm25 + (size_t)b * HWS;

    float o0 = 0.f, o1 = 0.f, o2 = 0.f, o3 = 0.f;
    #pragma unroll 1
    for (int k = 0; k < 9; k++) {
        float wk = c_wt[k];
        if (wk == 0.f) continue;         // warp-uniform skip

        float dy[4], dx[4];
        #pragma unroll
        for (int j = 0; j < 4; j++) { dy[j] = c_b2[2 * k]; dx[j] = c_b2[2 * k + 1]; }
        const int wbase_y = (2 * k) * 144;
        const int wbase_x = (2 * k + 1) * 144;
        #pragma unroll
        for (int ky = 0; ky < 3; ky++) {
            #pragma unroll
            for (int ci = 0; ci < 16; ci++) {
                const float* hrow = &s_h[(ci * HT + py + ky) * HP + px4];
                float4 A = *(const float4*)hrow;
                float2 C = *(const float2*)(hrow + 4);
                float in[6] = {A.x, A.y, A.z, A.w, C.x, C.y};
                const int wi = ci * 9 + ky * 3;
                #pragma unroll
                for (int kx = 0; kx < 3; kx++) {
                    const float wy = c_w2[wbase_y + wi + kx];
                    const float wx = c_w2[wbase_x + wi + kx];
                    #pragma unroll
                    for (int j = 0; j < 4; j++) {
                        dy[j] = fmaf(in[j + kx], wy, dy[j]);
                        dx[j] = fmaf(in[j + kx], wx, dx[j]);
                    }
                }
            }
        }

        const float kyo = (float)(k / 3 - 1);
        const float kxo = (float)(k % 3 - 1);
        #pragma unroll
        for (int j = 0; j < 4; j++) {
            float py_ = (float)gy + kyo + dy[j];
            float px_ = (float)(gx0 + j) + kxo + dx[j];
            float y0f = floorf(py_), x0f = floorf(px_);
            float wy = py_ - y0f, wx = px_ - x0f;
            int y0 = (int)y0f, x0 = (int)x0f;
            int y1 = y0 + 1,   x1 = x0 + 1;
            bool vy0 = (unsigned)y0 < HH, vy1 = (unsigned)y1 < HH;
            bool vx0 = (unsigned)x0 < WW, vx1 = (unsigned)x1 < WW;
            int yc0 = min(max(y0, 0), HH - 1), yc1 = min(max(y1, 0), HH - 1);
            int xc0 = min(max(x0, 0), WW - 1), xc1 = min(max(x1, 0), WW - 1);
            const float* r0 = pimg + yc0 * WW;
            const float* r1 = pimg + yc1 * WW;
            float v00 = (vy0 && vx0) ? r0[xc0] : 0.f;
            float v01 = (vy0 && vx1) ? r0[xc1] : 0.f;
            float v10 = (vy1 && vx0) ? r1[xc0] : 0.f;
            float v11 = (vy1 && vx1) ? r1[xc1] : 0.f;
            float samp = (1.f - wy) * (1.f - wx) * v00
                       + (1.f - wy) * wx         * v01
                       + wy         * (1.f - wx) * v10
                       + wy         * wx         * v11;
            if      (j == 0) o0 = fmaf(samp, wk, o0);
            else if (j == 1) o1 = fmaf(samp, wk, o1);
            else if (j == 2) o2 = fmaf(samp, wk, o2);
            else             o3 = fmaf(samp, wk, o3);
        }
    }

    float4 res = make_float4(o0, o1, o2, o3);
    *(float4*)&out[(size_t)b * HWS + (size_t)gy * WW + gx0] = res;
}

extern "C" void kernel_launch(void* const* d_in, const int* in_sizes, int n_in,
                              void* d_out, int out_size) {
    const float* pm25 = (const float*)d_in[0];
    const float* wind = (const float*)d_in[1];
    const float* topo = (const float*)d_in[2];

    cudaFuncSetAttribute(fused_residual_advection,
                         cudaFuncAttributeMaxDynamicSharedMemorySize, SMEM_BYTES);

    cudaMemcpyToSymbolAsync(c_w1, d_in[3], 432  * sizeof(float), 0, cudaMemcpyDeviceToDevice);
    cudaMemcpyToSymbolAsync(c_b1, d_in[4], 16   * sizeof(float), 0, cudaMemcpyDeviceToDevice);
    cudaMemcpyToSymbolAsync(c_w2, d_in[5], 2592 * sizeof(float), 0, cudaMemcpyDeviceToDevice);
    cudaMemcpyToSymbolAsync(c_b2, d_in[6], 18   * sizeof(float), 0, cudaMemcpyDeviceToDevice);
    cudaMemcpyToSymbolAsync(c_wt, d_in[7], 9    * sizeof(float), 0, cudaMemcpyDeviceToDevice);

    float* out = (float*)d_out;
    int B = in_sizes[0] / (HH * WW);
    dim3 grid(WW / TS, HH / TS, B);
    fused_residual_advection<<<grid, 256, SMEM_BYTES>>>(pm25, wind, topo, out);
}

// round 10
// speedup vs baseline: 1.4301x; 1.4301x over previous
#include <cuda_runtime.h>
#include <cuda_bf16.h>

// R10: split kernels.
//  A: conv1(3->16,3x3,pad1)+exact GELU  -> g_h[b][ci][y][x] (__device__, 64MB)
//  B: conv2(16->18,3x3,pad1 on h) per nonzero deform tap + bilinear sampling.

#define HH 512
#define WW 512
#define HWS (HH * WW)
#define BMAX 8

__constant__ float c_w1[432];    // (16,3,3,3)
__constant__ float c_b1[16];
__constant__ float c_w2[2592];   // (18,16,3,3)
__constant__ float c_b2[18];
__constant__ float c_wt[9];

// intermediate h, channel-plane major: [b][ci][y][x]
__device__ float g_h[BMAX * 16 * HWS];

// exact GELU via Abramowitz-Stegun 7.1.26 erf (|abs err| <= 1.5e-7)
__device__ __forceinline__ float gelu_fast(float x) {
    float z = 0.70710678118f * x;
    float a = fabsf(z);
    float t = __fdividef(1.0f, fmaf(0.3275911f, a, 1.0f));
    float p = fmaf(1.061405429f, t, -1.453152027f);
    p = fmaf(p, t, 1.421413741f);
    p = fmaf(p, t, -0.284496736f);
    p = fmaf(p, t, 0.254829592f);
    p = p * t;
    float e = __expf(-a * a);
    float erfa = fmaf(-p, e, 1.0f);
    float erfz = copysignf(erfa, z);
    return x * (0.5f * (1.0f + erfz));
}

// ---------------- Kernel A: conv1 + GELU, 2 px/thread, 1 row/block ----------
__global__ __launch_bounds__(256)
void conv1_gelu_kernel(const float* __restrict__ wind,
                       const float* __restrict__ topo) {
    const int b   = blockIdx.z;
    const int y   = blockIdx.y;
    const int gx0 = threadIdx.x * 2;          // 0..510

    const float* src[3];
    src[0] = wind + (size_t)b * 2 * HWS;
    src[1] = src[0] + HWS;
    src[2] = topo + (size_t)b * HWS;

    const bool ml = gx0 > 0;                  // col gx0-1 valid
    const bool mr = gx0 + 2 < WW;             // col gx0+2 valid
    const int  xl = max(gx0 - 1, 0);
    const int  xr = min(gx0 + 2, WW - 1);

    float in_reg[3][3][4];
    #pragma unroll
    for (int c = 0; c < 3; c++) {
        #pragma unroll
        for (int r = 0; r < 3; r++) {
            int ry = y - 1 + r;
            bool rok = (unsigned)ry < HH;
            const float* row = src[c] + min(max(ry, 0), HH - 1) * WW;
            float a = row[xl];
            float2 m = *(const float2*)&row[gx0];
            float d = row[xr];
            in_reg[c][r][0] = (rok && ml) ? a   : 0.f;
            in_reg[c][r][1] = rok         ? m.x : 0.f;
            in_reg[c][r][2] = rok         ? m.y : 0.f;
            in_reg[c][r][3] = (rok && mr) ? d   : 0.f;
        }
    }

    float* hb = g_h + (size_t)b * 16 * HWS + (size_t)y * WW + gx0;
    #pragma unroll
    for (int o = 0; o < 16; o++) {
        float a0 = c_b1[o], a1 = a0;
        #pragma unroll
        for (int c = 0; c < 3; c++)
            #pragma unroll
            for (int r = 0; r < 3; r++)
                #pragma unroll
                for (int kx = 0; kx < 3; kx++) {
                    const float w = c_w1[o * 27 + (c * 3 + r) * 3 + kx];
                    a0 = fmaf(in_reg[c][r][kx],     w, a0);
                    a1 = fmaf(in_reg[c][r][kx + 1], w, a1);
                }
        *(float2*)&hb[(size_t)o * HWS] = make_float2(gelu_fast(a0), gelu_fast(a1));
    }
}

// ---------------- Kernel B: conv2 per tap + bilinear, 4 px/thread -----------
__global__ __launch_bounds__(256)
void deform_kernel(const float* __restrict__ pm25,
                   float* __restrict__ out) {
    const int tid = threadIdx.x;
    const int b   = blockIdx.z;
    const int gy  = blockIdx.y * 2 + (tid >> 7);     // 0..511
    const int gx0 = (tid & 127) * 4;                 // 0..508

    const float* hb   = g_h + (size_t)b * 16 * HWS;
    const float* pimg = pm25 + (size_t)b * HWS;

    const bool ml = gx0 > 0;
    const bool mr = gx0 + 4 < WW;          // gx0+4 == 512 only when gx0 == 508
    const int  xl = max(gx0 - 1, 0);
    const int  xr = min(gx0 + 4, WW - 1);

    float o0 = 0.f, o1 = 0.f, o2 = 0.f, o3 = 0.f;
    #pragma unroll 1
    for (int k = 0; k < 9; k++) {
        float wk = c_wt[k];
        if (wk == 0.f) continue;           // warp-uniform skip

        float dy[4], dx[4];
        #pragma unroll
        for (int j = 0; j < 4; j++) { dy[j] = c_b2[2 * k]; dx[j] = c_b2[2 * k + 1]; }
        const int wbase_y = (2 * k) * 144;
        const int wbase_x = (2 * k + 1) * 144;

        #pragma unroll
        for (int ky = 0; ky < 3; ky++) {
            const int ry = gy - 1 + ky;
            if ((unsigned)ry >= HH) continue;   // warp-uniform: zero rows contribute nothing
            const float* hrow0 = hb + (size_t)ry * WW;
            #pragma unroll
            for (int ci = 0; ci < 16; ci++) {
                const float* hrow = hrow0 + (size_t)ci * HWS;
                float  l = hrow[xl];
                float4 m = *(const float4*)&hrow[gx0];
                float  r = hrow[xr];
                float in[6];
                in[0] = ml ? l : 0.f;
                in[1] = m.x; in[2] = m.y; in[3] = m.z; in[4] = m.w;
                in[5] = mr ? r : 0.f;
                const int wi = ci * 9 + ky * 3;
                #pragma unroll
                for (int kx = 0; kx < 3; kx++) {
                    const float wy = c_w2[wbase_y + wi + kx];
                    const float wx = c_w2[wbase_x + wi + kx];
                    #pragma unroll
                    for (int j = 0; j < 4; j++) {
                        dy[j] = fmaf(in[j + kx], wy, dy[j]);
                        dx[j] = fmaf(in[j + kx], wx, dx[j]);
                    }
                }
            }
        }

        const float kyo = (float)(k / 3 - 1);
        const float kxo = (float)(k % 3 - 1);
        #pragma unroll
        for (int j = 0; j < 4; j++) {
            float py_ = (float)gy + kyo + dy[j];
            float px_ = (float)(gx0 + j) + kxo + dx[j];
            float y0f = floorf(py_), x0f = floorf(px_);
            float wy = py_ - y0f, wx = px_ - x0f;
            int y0 = (int)y0f, x0 = (int)x0f;
            int y1 = y0 + 1,   x1 = x0 + 1;
            bool vy0 = (unsigned)y0 < HH, vy1 = (unsigned)y1 < HH;
            bool vx0 = (unsigned)x0 < WW, vx1 = (unsigned)x1 < WW;
            int yc0 = min(max(y0, 0), HH - 1), yc1 = min(max(y1, 0), HH - 1);
            int xc0 = min(max(x0, 0), WW - 1), xc1 = min(max(x1, 0), WW - 1);
            const float* r0 = pimg + yc0 * WW;
            const float* r1 = pimg + yc1 * WW;
            float v00 = (vy0 && vx0) ? r0[xc0] : 0.f;
            float v01 = (vy0 && vx1) ? r0[xc1] : 0.f;
            float v10 = (vy1 && vx0) ? r1[xc0] : 0.f;
            float v11 = (vy1 && vx1) ? r1[xc1] : 0.f;
            float samp = (1.f - wy) * (1.f - wx) * v00
                       + (1.f - wy) * wx         * v01
                       + wy         * (1.f - wx) * v10
                       + wy         * wx         * v11;
            if      (j == 0) o0 = fmaf(samp, wk, o0);
            else if (j == 1) o1 = fmaf(samp, wk, o1);
            else if (j == 2) o2 = fmaf(samp, wk, o2);
            else             o3 = fmaf(samp, wk, o3);
        }
    }

    *(float4*)&out[(size_t)b * HWS + (size_t)gy * WW + gx0] =
        make_float4(o0, o1, o2, o3);
}

extern "C" void kernel_launch(void* const* d_in, const int* in_sizes, int n_in,
                              void* d_out, int out_size) {
    const float* pm25 = (const float*)d_in[0];
    const float* wind = (const float*)d_in[1];
    const float* topo = (const float*)d_in[2];

    cudaMemcpyToSymbolAsync(c_w1, d_in[3], 432  * sizeof(float), 0, cudaMemcpyDeviceToDevice);
    cudaMemcpyToSymbolAsync(c_b1, d_in[4], 16   * sizeof(float), 0, cudaMemcpyDeviceToDevice);
    cudaMemcpyToSymbolAsync(c_w2, d_in[5], 2592 * sizeof(float), 0, cudaMemcpyDeviceToDevice);
    cudaMemcpyToSymbolAsync(c_b2, d_in[6], 18   * sizeof(float), 0, cudaMemcpyDeviceToDevice);
    cudaMemcpyToSymbolAsync(c_wt, d_in[7], 9    * sizeof(float), 0, cudaMemcpyDeviceToDevice);

    float* out = (float*)d_out;
    int B = in_sizes[0] / (HH * WW);

    dim3 gridA(1, HH, B);       // one 512-px row per block, 2 px/thread
    conv1_gelu_kernel<<<gridA, 256>>>(wind, topo);

    dim3 gridB(1, HH / 2, B);   // two rows per block, 4 px/thread
    deform_kernel<<<gridB, 256>>>(pm25, out);
}